// round 16
// baseline (speedup 1.0000x reference)
#include <cuda_runtime.h>
#include <cstdint>

// CorrelationHead fused. cp.async.bulk staging (4 racing c-quarters),
// 448 threads/block x 4 blocks/SM = 56 warps/SM for latency coverage.
// out[b,o] = bias[o] + sum over 625 in-bounds (i,j,u,v):
//   W[o, p*1029+q*49+i*7+j] * dot_c( P1[b,c,i,j], P2[b,c,u,v] ),
//   u = i+2(p-10), v = j+2(q-10) in [0,6]; u≡i (mod 2), v≡j (mod 2).
//
// tid = slot*8 + cs. slot = r*4 + ijq, r = (v&1)*7 + u. warp w <-> r = w.
// c = cs + 8*cl, cl = 0..15. Per iter: 8 LDS.32 -> 16 FMAs (4 ij x 4 v).
// Epilogue: reduce-scatter over cs (lane cs ends with taps 2cs,2cs+1),
// then per-lane W loads, then warp allreduce of the 4 outputs.

static constexpr int FEAT = 21609;          // 21*21*49
static constexpr int TEN  = 6272;           // 128*49 floats per tensor per batch
static constexpr int CH_F = TEN / 4;        // 1568 floats per c-quarter
static constexpr int CH_B = CH_F * 4;       // 6272 bytes
static constexpr int S2_OFF   = TEN;
static constexpr int WRED_OFF = 2 * TEN + 16;          // after 16-float OOB pad
static constexpr int MBAR_B   = (WRED_OFF + 64) * 4;   // byte offset of mbarriers
static constexpr int SMEM_BYTES = MBAR_B + 32;         // four 8B mbarriers

__global__ __launch_bounds__(448, 4)
void corr_head_kernel(const float* __restrict__ p1,
                      const float* __restrict__ p2,
                      const float* __restrict__ W,
                      const float* __restrict__ bias,
                      float* __restrict__ out)
{
    extern __shared__ float sm[];
    float* s1   = sm;             // P1 raw: [c*49 + uv]
    float* s2   = sm + S2_OFF;    // P2 raw: [c*49 + uv]
    float* wred = sm + WRED_OFF;  // 14 warps * 4 outputs

    uint32_t smem_u32;
    asm("{ .reg .u64 t; cvta.to.shared.u64 t, %1; cvt.u32.u64 %0, t; }"
        : "=r"(smem_u32) : "l"(sm));

    const int b   = blockIdx.x;
    const int tid = threadIdx.x;
    const float* p1b = p1 + (size_t)b * TEN;
    const float* p2b = p2 + (size_t)b * TEN;

    // ---- Init mbarriers + zero OOB pad ----
    if (tid < 4)
        asm volatile("mbarrier.init.shared.b64 [%0], 1;"
                     :: "r"(smem_u32 + MBAR_B + 8 * tid) : "memory");
    if (tid >= 8 && tid < 24) sm[2 * TEN + (tid - 8)] = 0.f;
    __syncthreads();

    // ---- Issue bulk copies: thread k owns c-quarter k (copies race) ----
    if (tid < 4) {
        const int k = tid;
        const uint32_t mb = smem_u32 + MBAR_B + 8 * k;
        const uint32_t d1 = smem_u32 + k * CH_B;
        const uint32_t d2 = smem_u32 + TEN * 4 + k * CH_B;
        asm volatile("mbarrier.arrive.expect_tx.shared.b64 _, [%0], %1;"
                     :: "r"(mb), "r"(2 * CH_B) : "memory");
        asm volatile("cp.async.bulk.shared::cluster.global.mbarrier::complete_tx::bytes [%0], [%1], %2, [%3];"
                     :: "r"(d1), "l"(p1b + k * CH_F), "r"(CH_B), "r"(mb) : "memory");
        asm volatile("cp.async.bulk.shared::cluster.global.mbarrier::complete_tx::bytes [%0], [%1], %2, [%3];"
                     :: "r"(d2), "l"(p2b + k * CH_F), "r"(CH_B), "r"(mb) : "memory");
    }

    // ---- Per-thread geometry ----
    const int cs   = tid & 7;
    const int slot = tid >> 3;          // 0..55
    const int r    = slot >> 2;         // 0..13 (== warp id)
    const int ijq  = slot & 3;
    const int jpar = (r >= 7) ? 1 : 0;
    const int u    = r - jpar * 7;
    const int ipar = u & 1;
    const int ni   = 4 - ipar;
    const int nj   = 4 - jpar;

    int xb[4];
    #pragma unroll
    for (int t = 0; t < 4; t++) {
        int idx = ijq * 4 + t;
        int a_  = (nj == 4) ? (idx >> 2) : (idx / 3);
        int b_  = idx - a_ * nj;
        int ij  = (ipar + 2 * a_) * 7 + (jpar + 2 * b_);
        xb[t]   = ((idx < ni * nj) ? ij : 0) + cs * 49;
    }
    const int yb = u * 7 + jpar + cs * 49;

    // ---- Accumulators: d[tq*4 + vi] ----
    float d[16];
    #pragma unroll
    for (int t = 0; t < 16; t++) d[t] = 0.f;

    #define MBAR_WAIT(mb) do {                                                    \
        asm volatile("{\n\t.reg .pred P;\n\t"                                     \
                     "WL_%=:\n\t"                                                 \
                     "mbarrier.try_wait.parity.acquire.cta.shared::cta.b64 P, [%0], 0, 0x989680;\n\t" \
                     "@!P bra WL_%=;\n\t}"                                        \
                     :: "r"(mb) : "memory");                                      \
    } while (0)

    #define BODY(cl) do {                                                         \
        const int off = (cl) * 392;                                               \
        float y0 = s2[yb + off];                                                  \
        float y1 = s2[yb + off + 2];                                              \
        float y2 = s2[yb + off + 4];                                              \
        float y3 = s2[yb + off + 6];                                              \
        float x0 = s1[xb[0] + off];                                               \
        float x1 = s1[xb[1] + off];                                               \
        float x2 = s1[xb[2] + off];                                               \
        float x3 = s1[xb[3] + off];                                               \
        d[0]  = fmaf(x0, y0, d[0]);  d[1]  = fmaf(x0, y1, d[1]);                  \
        d[2]  = fmaf(x0, y2, d[2]);  d[3]  = fmaf(x0, y3, d[3]);                  \
        d[4]  = fmaf(x1, y0, d[4]);  d[5]  = fmaf(x1, y1, d[5]);                  \
        d[6]  = fmaf(x1, y2, d[6]);  d[7]  = fmaf(x1, y3, d[7]);                  \
        d[8]  = fmaf(x2, y0, d[8]);  d[9]  = fmaf(x2, y1, d[9]);                  \
        d[10] = fmaf(x2, y2, d[10]); d[11] = fmaf(x2, y3, d[11]);                 \
        d[12] = fmaf(x3, y0, d[12]); d[13] = fmaf(x3, y1, d[13]);                 \
        d[14] = fmaf(x3, y2, d[14]); d[15] = fmaf(x3, y3, d[15]);                 \
    } while (0)

    // ---- 4-quarter pipeline: quarter k covers cl = 4k..4k+3 ----
    MBAR_WAIT(smem_u32 + MBAR_B);
    BODY(0); BODY(1); BODY(2); BODY(3);
    MBAR_WAIT(smem_u32 + MBAR_B + 8);
    BODY(4); BODY(5); BODY(6); BODY(7);
    MBAR_WAIT(smem_u32 + MBAR_B + 16);
    BODY(8); BODY(9); BODY(10); BODY(11);
    MBAR_WAIT(smem_u32 + MBAR_B + 24);
    BODY(12); BODY(13); BODY(14); BODY(15);

    #undef BODY
    #undef MBAR_WAIT

    // ---- Reduce-scatter over the 8 cs lanes: lane cs ends with taps 2cs, 2cs+1 ----
    const unsigned FULL = 0xffffffffu;
    #pragma unroll
    for (int k = 0; k < 8; k++) {                     // tap bit2 <- cs bit2
        float give = (cs & 4) ? d[k] : d[k + 8];
        float got  = __shfl_xor_sync(FULL, give, 4);
        d[k] = ((cs & 4) ? d[k + 8] : d[k]) + got;
    }
    #pragma unroll
    for (int k = 0; k < 4; k++) {                     // tap bit1 <- cs bit1
        float give = (cs & 2) ? d[k] : d[k + 4];
        float got  = __shfl_xor_sync(FULL, give, 2);
        d[k] = ((cs & 2) ? d[k + 4] : d[k]) + got;
    }
    #pragma unroll
    for (int k = 0; k < 2; k++) {                     // tap bit0 <- cs bit0
        float give = (cs & 1) ? d[k] : d[k + 2];
        float got  = __shfl_xor_sync(FULL, give, 1);
        d[k] = ((cs & 1) ? d[k + 2] : d[k]) + got;
    }
    // Lane cs now holds taps T = 2*cs and T+1 in d[0], d[1] (T = tq*4 + vi).

    // ---- Per-lane W combine: tap (tq = cs>>1, vi = 2*(cs&1) and +1) ----
    float part[4] = {0.f, 0.f, 0.f, 0.f};
    {
        const int tq  = cs >> 1;
        const int vi0 = 2 * (cs & 1);
        const int idx = ijq * 4 + tq;
        if (idx < ni * nj) {
            int a_  = (nj == 4) ? (idx >> 2) : (idx / 3);
            int b_  = idx - a_ * nj;
            int ij  = (ipar + 2 * a_) * 7 + (jpar + 2 * b_);
            int wb  = (10 + (u >> 1) - a_) * 1029 + (10 - b_) * 49 + ij;
            int f0  = wb + vi0 * 49;
            bool hi = (vi0 + 1) < (4 - jpar);         // vi=3 invalid when jpar=1
            #pragma unroll
            for (int o = 0; o < 4; o++) {
                part[o] = fmaf(d[0], __ldg(W + o * FEAT + f0), part[o]);
                if (hi)
                    part[o] = fmaf(d[1], __ldg(W + o * FEAT + f0 + 49), part[o]);
            }
        }
    }

    // ---- Warp allreduce of the 4 outputs (all 32 lanes same r-row sum) ----
    #pragma unroll
    for (int off = 16; off; off >>= 1) {
        part[0] += __shfl_xor_sync(FULL, part[0], off);
        part[1] += __shfl_xor_sync(FULL, part[1], off);
        part[2] += __shfl_xor_sync(FULL, part[2], off);
        part[3] += __shfl_xor_sync(FULL, part[3], off);
    }
    const int lane = tid & 31;
    if (lane < 4) wred[(tid >> 5) * 4 + lane] = part[lane];
    __syncthreads();

    if (tid < 4) {
        float s = __ldg(bias + tid);
        #pragma unroll
        for (int w = 0; w < 14; w++) s += wred[w * 4 + tid];
        out[b * 4 + tid] = s;
    }
}

extern "C" void kernel_launch(void* const* d_in, const int* in_sizes, int n_in,
                              void* d_out, int out_size)
{
    (void)in_sizes; (void)n_in; (void)out_size;
    const float* p1 = (const float*)d_in[0];   // patch1 [512,128,7,7]
    const float* p2 = (const float*)d_in[1];   // patch2 [512,128,7,7]
    const float* W  = (const float*)d_in[2];   // w_bbox [4,21609]
    const float* bb = (const float*)d_in[3];   // b_bbox [4]
    float* out = (float*)d_out;                // [512,4] fp32

    cudaFuncSetAttribute(corr_head_kernel,
                         cudaFuncAttributeMaxDynamicSharedMemorySize, SMEM_BYTES);

    corr_head_kernel<<<512, 448, SMEM_BYTES>>>(p1, p2, W, bb, out);
}